// round 11
// baseline (speedup 1.0000x reference)
#include <cuda_runtime.h>

#define BATCH 4096
#define NCLS  10000
#define DIM   256
#define ALPHA 0.5f
#define CAP   64   // per-class row-list capacity (overflow handled exactly)

// Scratch (allocation-free: __device__ globals).
// g_cnt starts zeroed (static init); K2 re-zeroes ONLY touched classes
// (untouched are already 0) -> no zero kernel, no extra counter copies:
// in K2 a whole class row is owned by ONE warp, so read-then-clean is
// ordered by warp program order.
__device__ int g_cnt[NCLS];         // per-class sample count
__device__ int g_label[BATCH];      // decoded label per row (overflow fallback)
__device__ int g_rows[NCLS * CAP];  // per-class row index list (8B aligned rows)

// ---------------------------------------------------------------------------
// K1: one block per batch row — BARRIER-FREE scan.
// Warp w scans 1 KB strips at stride 8 KB (2 co-issued float4/lane). Early
// exit via volatile shared flag polled under the LDG shadow (LDS ~29 cyc,
// hidden by the in-flight loads). No BAR.SYNC in the scan loop: warps drift
// independently, keeping loads continuously in flight instead of
// lock-stepping on the block's slowest DRAM load each chunk.
// A finder always exists (true one-hot), so the post-loop spin terminates.
// ---------------------------------------------------------------------------
__global__ __launch_bounds__(256, 8)
void scan_loss_kernel(const float* __restrict__ onehot,
                      const float* __restrict__ feat,
                      const float* __restrict__ centers,
                      float* __restrict__ loss_out) {
    const int b    = blockIdx.x;
    const int t    = threadIdx.x;
    const int warp = t >> 5;
    const int lane = t & 31;

    __shared__ volatile int s_label;
    __shared__ float s_red[8];
    if (t == 0) s_label = -1;
    __syncthreads();  // publish the -1 init (only barrier before the scan)

    const float4* row = reinterpret_cast<const float4*>(onehot + (size_t)b * NCLS);
    const int NV4 = NCLS / 4;  // 2500 float4s

    // super-iteration covers 512 float4 (8 warps x 64); ceil(2500/512) = 5
    #pragma unroll 1
    for (int it = 0; it < 5; ++it) {
        const int base = (it * 8 + warp) * 64;
        const int i0 = base + lane;
        const int i1 = base + lane + 32;
        float4 v0 = make_float4(0.f, 0.f, 0.f, 0.f);
        float4 v1 = make_float4(0.f, 0.f, 0.f, 0.f);
        if (i0 < NV4) v0 = row[i0];   // both loads in flight (MLP=2)
        if (i1 < NV4) v1 = row[i1];
        const int fl = s_label;        // LDS poll, hidden under LDG latency
        if (fl >= 0) break;
        int found = -1;
        if (v0.x != 0.f)      found = 4 * i0 + 0;
        else if (v0.y != 0.f) found = 4 * i0 + 1;
        else if (v0.z != 0.f) found = 4 * i0 + 2;
        else if (v0.w != 0.f) found = 4 * i0 + 3;
        else if (v1.x != 0.f) found = 4 * i1 + 0;
        else if (v1.y != 0.f) found = 4 * i1 + 1;
        else if (v1.z != 0.f) found = 4 * i1 + 2;
        else if (v1.w != 0.f) found = 4 * i1 + 3;
        if (found >= 0) {
            g_label[b] = found;
            int slot = atomicAdd(&g_cnt[found], 1);
            if (slot < CAP) g_rows[found * CAP + slot] = b;
            s_label = found;           // release the block
            break;
        }
    }

    // wait until the finder has published (loop may end before STS lands)
    while (s_label < 0) {}
    const int label = s_label;

    // loss vs OLD centers (thread t owns dim t)
    float f = feat[(size_t)b * DIM + t];
    float c = centers[(size_t)label * DIM + t];
    float d = f - c;
    float sq = d * d;
    #pragma unroll
    for (int off = 16; off > 0; off >>= 1)
        sq += __shfl_down_sync(0xFFFFFFFFu, sq, off);
    if (lane == 0) s_red[warp] = sq;
    __syncthreads();
    if (t < 8) {
        float v = s_red[t];
        #pragma unroll
        for (int off = 4; off > 0; off >>= 1)
            v += __shfl_down_sync(0xFFu, v, off);
        if (t == 0) loss_out[b] = v;
    }
}

// ---------------------------------------------------------------------------
// K2: one WARP per class row (2 float4 per lane, 10000 warps = 1250 blocks
// = 1.06 waves). ALL lanes load g_cnt[c] (same address -> 1-sector
// broadcast LDG; no shfl, no lane-0 serialization). n==0 fast path (66% of
// classes, warp-uniform branch): verbatim centers copy, no division, no
// row-list use, no counter store. n>=1: lane 0 cleans the counter AFTER the
// warp-wide load in program order -> race-free with zero barriers; up to 4
// independent feat gathers in flight.
// ---------------------------------------------------------------------------
__global__ __launch_bounds__(256)
void scale_gather_kernel(const float* __restrict__ centers,
                         const float* __restrict__ feat,
                         float* __restrict__ out_centers) {
    const int c    = (blockIdx.x * blockDim.x + threadIdx.x) >> 5;  // class; grid exact
    const int lane = threadIdx.x & 31;

    // level 0: count (broadcast), row slots (broadcast), centers — independent
    const int n = g_cnt[c];
    const int2 r01 = *reinterpret_cast<const int2*>(&g_rows[c * CAP]);
    const float4* crow = reinterpret_cast<const float4*>(centers) + (size_t)c * 64;
    float4 a0 = crow[lane];
    float4 a1 = crow[lane + 32];
    float4* orow = reinterpret_cast<float4*>(out_centers) + (size_t)c * 64;

    if (n == 0) {  // 66% of classes: pure copy, counter already zero
        orow[lane]      = a0;
        orow[lane + 32] = a1;
        return;
    }

    // self-clean in warp program order (warp-wide LDG above precedes this STG)
    if (lane == 0) g_cnt[c] = 0;

    const float fn = (float)n;
    const float s = __fdividef(ALPHA, fn + 1.0f);
    const float k = 1.0f - fn * s;
    a0.x *= k; a0.y *= k; a0.z *= k; a0.w *= k;
    a1.x *= k; a1.y *= k; a1.z *= k; a1.w *= k;

    const float4* feat4 = reinterpret_cast<const float4*>(feat);

    // n<=2 covers 99.4% of touched classes; all gathers co-issued (MLP<=4)
    float4 f00 = feat4[(size_t)r01.x * 64 + lane];
    float4 f01 = feat4[(size_t)r01.x * 64 + lane + 32];
    float4 f10 = make_float4(0.f, 0.f, 0.f, 0.f);
    float4 f11 = make_float4(0.f, 0.f, 0.f, 0.f);
    if (n >= 2) {
        f10 = feat4[(size_t)r01.y * 64 + lane];
        f11 = feat4[(size_t)r01.y * 64 + lane + 32];
    }
    a0.x += s * (f00.x + f10.x); a0.y += s * (f00.y + f10.y);
    a0.z += s * (f00.z + f10.z); a0.w += s * (f00.w + f10.w);
    a1.x += s * (f01.x + f11.x); a1.y += s * (f01.y + f11.y);
    a1.z += s * (f01.z + f11.z); a1.w += s * (f01.w + f11.w);

    if (n > 2) {
        const int m = (n <= CAP) ? n : CAP;
        #pragma unroll 1
        for (int j = 2; j < m; ++j) {
            int bj = g_rows[c * CAP + j];
            float4 g0 = feat4[(size_t)bj * 64 + lane];
            float4 g1 = feat4[(size_t)bj * 64 + lane + 32];
            a0.x += s * g0.x; a0.y += s * g0.y; a0.z += s * g0.z; a0.w += s * g0.w;
            a1.x += s * g1.x; a1.y += s * g1.y; a1.z += s * g1.z; a1.w += s * g1.w;
        }
        if (n > CAP) {
            // exhaustive fallback (statistically unreachable; exact)
            #pragma unroll 1
            for (int bb = 0; bb < BATCH; ++bb) {
                if (g_label[bb] == c) {
                    bool seen = false;
                    for (int j = 0; j < CAP; ++j)
                        if (g_rows[c * CAP + j] == bb) { seen = true; break; }
                    if (!seen) {
                        float4 g0 = feat4[(size_t)bb * 64 + lane];
                        float4 g1 = feat4[(size_t)bb * 64 + lane + 32];
                        a0.x += s * g0.x; a0.y += s * g0.y;
                        a0.z += s * g0.z; a0.w += s * g0.w;
                        a1.x += s * g1.x; a1.y += s * g1.y;
                        a1.z += s * g1.z; a1.w += s * g1.w;
                    }
                }
            }
        }
    }

    orow[lane]      = a0;
    orow[lane + 32] = a1;
}

// ---------------------------------------------------------------------------
extern "C" void kernel_launch(void* const* d_in, const int* in_sizes, int n_in,
                              void* d_out, int out_size) {
    const float* feat    = (const float*)d_in[0];  // [4096, 256]
    const float* onehot  = (const float*)d_in[1];  // [4096, 10000]
    const float* centers = (const float*)d_in[2];  // [10000, 256]

    float* loss_out    = (float*)d_out;            // [4096]
    float* centers_out = (float*)d_out + BATCH;    // [10000, 256]

    scan_loss_kernel<<<BATCH, 256>>>(onehot, feat, centers, loss_out);
    // 10000 classes, one warp each -> 1250 blocks of 256 threads (exact)
    scale_gather_kernel<<<NCLS * 32 / 256, 256>>>(centers, feat, centers_out);
}

// round 12
// speedup vs baseline: 1.1007x; 1.1007x over previous
#include <cuda_runtime.h>

#define BATCH 4096
#define NCLS  10000
#define DIM   256
#define ALPHA 0.5f
#define CAP   64   // per-class row-list capacity (overflow handled exactly)

// Scratch (allocation-free: __device__ globals).
// g_cnt starts zeroed (static init); K2 re-zeroes ONLY touched classes
// (untouched are already 0) -> no zero kernel.
__device__ int g_cnt[NCLS];         // per-class sample count
__device__ int g_label[BATCH];      // decoded label per row (overflow fallback)
__device__ int g_rows[NCLS * CAP];  // per-class row index list (8B aligned rows)

// ---------------------------------------------------------------------------
// K1: ONE WARP PER ROW. Zero barriers, zero shared memory, zero cross-warp
// coordination. 4096 warps = 512 blocks = ~1 wave.
// Scan: 2 KB per iteration (4 float4/lane), software-pipelined depth 1 so
// ~4 LDGs stay in flight per warp while the previous buffer is tested via
// __ballot_sync (warp-internal, ~15 cyc). Expected read ~20 KB + ~2 KB
// overshoot per 40 KB row.
// Loss: lane owns 8 consecutive dims (2 float4 of feat + centers), one
// shfl-tree reduce.
// ---------------------------------------------------------------------------
__global__ __launch_bounds__(256, 4)
void scan_loss_kernel(const float* __restrict__ onehot,
                      const float* __restrict__ feat,
                      const float* __restrict__ centers,
                      float* __restrict__ loss_out) {
    const int lane = threadIdx.x & 31;
    const int b    = blockIdx.x * 8 + (threadIdx.x >> 5);  // row for this warp

    const float4* row = reinterpret_cast<const float4*>(onehot + (size_t)b * NCLS);
    const int NV4 = NCLS / 4;            // 2500 float4
    const int PER_IT = 128;              // float4 per iteration (32 lanes x 4)
    const int NIT = (NV4 + PER_IT - 1) / PER_IT;  // 20

    float4 buf[4];
    // prime the pipeline: iteration 0
    #pragma unroll
    for (int k = 0; k < 4; ++k) {
        int i = lane + 32 * k;
        buf[k] = (i < NV4) ? row[i] : make_float4(0.f, 0.f, 0.f, 0.f);
    }

    int label = -1;
    #pragma unroll 1
    for (int it = 0; it < NIT; ++it) {
        // issue next iteration's loads BEFORE testing the current buffer
        float4 nxt[4];
        if (it + 1 < NIT) {
            #pragma unroll
            for (int k = 0; k < 4; ++k) {
                int i = (it + 1) * PER_IT + lane + 32 * k;
                nxt[k] = (i < NV4) ? row[i] : make_float4(0.f, 0.f, 0.f, 0.f);
            }
        }
        // test current buffer
        int found = -1;
        const int base = it * PER_IT;
        #pragma unroll
        for (int k = 0; k < 4; ++k) {
            int i = base + lane + 32 * k;
            if (buf[k].x != 0.f)      found = 4 * i + 0;
            else if (buf[k].y != 0.f) found = 4 * i + 1;
            else if (buf[k].z != 0.f) found = 4 * i + 2;
            else if (buf[k].w != 0.f) found = 4 * i + 3;
        }
        unsigned m = __ballot_sync(0xFFFFFFFFu, found >= 0);
        if (m) {
            const int src = __ffs(m) - 1;          // exactly one lane finds it
            if (lane == src) {
                g_label[b] = found;
                int slot = atomicAdd(&g_cnt[found], 1);
                if (slot < CAP) g_rows[found * CAP + slot] = b;
            }
            label = __shfl_sync(0xFFFFFFFFu, found, src);
            break;
        }
        #pragma unroll
        for (int k = 0; k < 4; ++k) buf[k] = nxt[k];
    }

    // loss vs OLD centers: lane owns dims [lane*8, lane*8+8)
    const float4* frow = reinterpret_cast<const float4*>(feat + (size_t)b * DIM);
    const float4* crow = reinterpret_cast<const float4*>(centers + (size_t)label * DIM);
    float4 fA = frow[lane * 2], fB = frow[lane * 2 + 1];
    float4 cA = crow[lane * 2], cB = crow[lane * 2 + 1];
    float dx, sq;
    dx = fA.x - cA.x; sq  = dx * dx;
    dx = fA.y - cA.y; sq += dx * dx;
    dx = fA.z - cA.z; sq += dx * dx;
    dx = fA.w - cA.w; sq += dx * dx;
    dx = fB.x - cB.x; sq += dx * dx;
    dx = fB.y - cB.y; sq += dx * dx;
    dx = fB.z - cB.z; sq += dx * dx;
    dx = fB.w - cB.w; sq += dx * dx;
    #pragma unroll
    for (int off = 16; off > 0; off >>= 1)
        sq += __shfl_down_sync(0xFFFFFFFFu, sq, off);
    if (lane == 0) loss_out[b] = sq;
}

// ---------------------------------------------------------------------------
// K2: one WARP per class row (round-11 version, measured best: 8.16us).
// ALL lanes load g_cnt[c] (broadcast LDG). n==0 fast path (66% of classes):
// verbatim copy, no counter store. n>=1: lane 0 cleans counter after the
// warp-wide load (warp program order -> race-free, no barriers); up to 4
// independent feat gathers in flight.
// ---------------------------------------------------------------------------
__global__ __launch_bounds__(256)
void scale_gather_kernel(const float* __restrict__ centers,
                         const float* __restrict__ feat,
                         float* __restrict__ out_centers) {
    const int c    = (blockIdx.x * blockDim.x + threadIdx.x) >> 5;  // class; grid exact
    const int lane = threadIdx.x & 31;

    const int n = g_cnt[c];
    const int2 r01 = *reinterpret_cast<const int2*>(&g_rows[c * CAP]);
    const float4* crow = reinterpret_cast<const float4*>(centers) + (size_t)c * 64;
    float4 a0 = crow[lane];
    float4 a1 = crow[lane + 32];
    float4* orow = reinterpret_cast<float4*>(out_centers) + (size_t)c * 64;

    if (n == 0) {  // 66% of classes: pure copy, counter already zero
        orow[lane]      = a0;
        orow[lane + 32] = a1;
        return;
    }

    if (lane == 0) g_cnt[c] = 0;  // warp program order after the load: race-free

    const float fn = (float)n;
    const float s = __fdividef(ALPHA, fn + 1.0f);
    const float k = 1.0f - fn * s;
    a0.x *= k; a0.y *= k; a0.z *= k; a0.w *= k;
    a1.x *= k; a1.y *= k; a1.z *= k; a1.w *= k;

    const float4* feat4 = reinterpret_cast<const float4*>(feat);

    float4 f00 = feat4[(size_t)r01.x * 64 + lane];
    float4 f01 = feat4[(size_t)r01.x * 64 + lane + 32];
    float4 f10 = make_float4(0.f, 0.f, 0.f, 0.f);
    float4 f11 = make_float4(0.f, 0.f, 0.f, 0.f);
    if (n >= 2) {
        f10 = feat4[(size_t)r01.y * 64 + lane];
        f11 = feat4[(size_t)r01.y * 64 + lane + 32];
    }
    a0.x += s * (f00.x + f10.x); a0.y += s * (f00.y + f10.y);
    a0.z += s * (f00.z + f10.z); a0.w += s * (f00.w + f10.w);
    a1.x += s * (f01.x + f11.x); a1.y += s * (f01.y + f11.y);
    a1.z += s * (f01.z + f11.z); a1.w += s * (f01.w + f11.w);

    if (n > 2) {
        const int m = (n <= CAP) ? n : CAP;
        #pragma unroll 1
        for (int j = 2; j < m; ++j) {
            int bj = g_rows[c * CAP + j];
            float4 g0 = feat4[(size_t)bj * 64 + lane];
            float4 g1 = feat4[(size_t)bj * 64 + lane + 32];
            a0.x += s * g0.x; a0.y += s * g0.y; a0.z += s * g0.z; a0.w += s * g0.w;
            a1.x += s * g1.x; a1.y += s * g1.y; a1.z += s * g1.z; a1.w += s * g1.w;
        }
        if (n > CAP) {
            // exhaustive fallback (statistically unreachable; exact)
            #pragma unroll 1
            for (int bb = 0; bb < BATCH; ++bb) {
                if (g_label[bb] == c) {
                    bool seen = false;
                    for (int j = 0; j < CAP; ++j)
                        if (g_rows[c * CAP + j] == bb) { seen = true; break; }
                    if (!seen) {
                        float4 g0 = feat4[(size_t)bb * 64 + lane];
                        float4 g1 = feat4[(size_t)bb * 64 + lane + 32];
                        a0.x += s * g0.x; a0.y += s * g0.y;
                        a0.z += s * g0.z; a0.w += s * g0.w;
                        a1.x += s * g1.x; a1.y += s * g1.y;
                        a1.z += s * g1.z; a1.w += s * g1.w;
                    }
                }
            }
        }
    }

    orow[lane]      = a0;
    orow[lane + 32] = a1;
}

// ---------------------------------------------------------------------------
extern "C" void kernel_launch(void* const* d_in, const int* in_sizes, int n_in,
                              void* d_out, int out_size) {
    const float* feat    = (const float*)d_in[0];  // [4096, 256]
    const float* onehot  = (const float*)d_in[1];  // [4096, 10000]
    const float* centers = (const float*)d_in[2];  // [10000, 256]

    float* loss_out    = (float*)d_out;            // [4096]
    float* centers_out = (float*)d_out + BATCH;    // [10000, 256]

    // 4096 rows, one warp each -> 512 blocks of 8 warps (exact)
    scan_loss_kernel<<<BATCH / 8, 256>>>(onehot, feat, centers, loss_out);
    // 10000 classes, one warp each -> 1250 blocks of 256 threads (exact)
    scale_gather_kernel<<<NCLS * 32 / 256, 256>>>(centers, feat, centers_out);
}